// round 15
// baseline (speedup 1.0000x reference)
#include <cuda_runtime.h>
#include <cstdint>

// E=8192 envs, A=128 agents/env, K=512 passengers/env, P=E*K rows x 11 f32 cols.
// Inputs: passengers f32[P,11], accepts/picks bool->32bit [E,A], targets i32[E,A],
//         vectors f32[E,A,4], timesteps i32[E]. Output f32[P,11].
//
// Champion (R4) + single tweak: __launch_bounds__(256,7) to force <=36 regs ->
// 7 CTAs/SM (was 6 @ 40 regs), raising in-flight loads ~16% with per-thread
// MLP (6-deep float4 batch) unchanged. Everything else is the validated R4
// configuration: flags under load shadow, store burst after argmin, default
// cache policy, agent-driven sparse patches into L2-resident lines.

#define NENV   8192
#define NAG    128
#define NPASS  512
#define NTHR   256
#define ROWF   11
#define VEC4S  ((NPASS * ROWF) / 4)   // 1408 float4 per env chunk (22528 B)
#define TAIL   (VEC4S - 5 * NTHR)     // 128

__global__ __launch_bounds__(NTHR, 7)
void pst_kernel(const float* __restrict__ passengers,
                const unsigned int* __restrict__ accepts,
                const unsigned int* __restrict__ picks,
                const int* __restrict__ targets,
                const float* __restrict__ vectors,
                const int* __restrict__ timesteps,
                float* __restrict__ out)
{
    const int e   = blockIdx.x;
    const int tid = threadIdx.x;

    __shared__ int                cnt[NPASS];      // accept multiplicity per local passenger
    __shared__ unsigned char      picked[NPASS];   // zero-dist pick landed on this row
    __shared__ unsigned long long minkey;          // (dist_bits<<32)|agent argmin
    __shared__ float              ts_s;

    // ---------- phase 0: front-batch the streaming loads (HBM in flight early) ----------
    const float4* __restrict__ src = reinterpret_cast<const float4*>(passengers) + (size_t)e * VEC4S;
    float4*       __restrict__ dst = reinterpret_cast<float4*>(out) + (size_t)e * VEC4S;

    // small per-agent loads first so they're not queued behind 24KB of stream
    const float INF = __int_as_float(0x7f800000);
    float d  = INF;
    int   lt = 0;
    bool  acc = false, pk = false;
    float4 av;
    if (tid < NAG) {
        av  = reinterpret_cast<const float4*>(vectors)[(size_t)e * NAG + tid];
        lt  = __ldg(&targets[e * NAG + tid]) - e * NPASS;       // local idx in [0,512)
        acc = (accepts[e * NAG + tid] != 0u);                   // robust to i32/f32 widening
        pk  = (picks  [e * NAG + tid] != 0u);
    }

    float4 c0 = src[tid];
    float4 c1 = src[tid + 1 * NTHR];
    float4 c2 = src[tid + 2 * NTHR];
    float4 c3 = src[tid + 3 * NTHR];
    float4 c4 = src[tid + 4 * NTHR];
    float4 c5;
    if (tid < TAIL) c5 = src[tid + 5 * NTHR];

    // ---------- phase 1: flag resolution under the load shadow ----------
    for (int i = tid; i < NPASS; i += NTHR) { cnt[i] = 0; picked[i] = 0; }
    if (tid == 0) { ts_s = (float)__ldg(&timesteps[e]); minkey = ~0ull; }

    if (tid < NAG) {
        float dx = av.x - av.z, dy = av.y - av.w;
        d = sqrtf(dx * dx + dy * dy);
        if (av.x == -100.0f && av.y == -100.0f && av.z == -100.0f && av.w == -100.0f) d = INF;
    }
    __syncthreads();                                            // B1: smem init done

    if (acc) atomicAdd(&cnt[lt], 1);
    if (tid < NAG && pk && d < 1e-6f) picked[lt] = 1;
    __syncthreads();                                            // B2: counts + picked visible

    // dup mask + per-env argmin over where(dup, d, inf).
    // JAX argmin: first index achieving min; all-inf -> index 0. Key bits are
    // monotone in the (nonneg) distance; ties resolve to lowest agent index.
    // The reference while-loop converges in exactly one body call: the argmin
    // agent keeps its target, every other duplicate agent is removed.
    bool dup = acc && (cnt[lt] > 1);
    if (tid < NAG) {
        unsigned long long key =
            ((unsigned long long)__float_as_uint(dup ? d : INF) << 32) | (unsigned)tid;
        #pragma unroll
        for (int s = 16; s > 0; s >>= 1) {
            unsigned long long o = __shfl_down_sync(0xffffffffu, key, s);
            if (o < key) key = o;
        }
        if ((tid & 31) == 0) atomicMin(&minkey, key);
    }
    __syncthreads();                                            // B3: argmin resolved
    const int keep = (int)(minkey & 0xffffffffu);

    // ---------- phase 2: bulk store burst ----------
    dst[tid]            = c0;
    dst[tid + 1 * NTHR] = c1;
    dst[tid + 2 * NTHR] = c2;
    dst[tid + 3 * NTHR] = c3;
    dst[tid + 4 * NTHR] = c4;
    if (tid < TAIL) dst[tid + 5 * NTHR] = c5;
    __syncthreads();                                            // B4: bulk before patches

    // ---------- phase 3: agent-driven sparse patches ----------
    // At most one surviving accept agent per row -> unique writer for cols 7/9
    // (and 6 when no pick). Racing pick writers store identical values.
    if (tid < NAG) {
        const float ts = ts_s;
        float* row = reinterpret_cast<float*>(dst) + lt * ROWF;
        bool surviving = acc && !(dup && tid != keep);
        if (surviving) {
            row[7] = (float)tid;
            row[9] = ts;
            if (!picked[lt]) row[6] = 1.0f;
        }
        if (pk && d < 1e-6f) {
            row[6]  = 2.0f;
            row[10] = ts;
        }
    }
}

extern "C" void kernel_launch(void* const* d_in, const int* in_sizes, int n_in,
                              void* d_out, int out_size)
{
    const float*        passengers = (const float*)d_in[0];
    const unsigned int* accepts    = (const unsigned int*)d_in[1];
    const unsigned int* picks      = (const unsigned int*)d_in[2];
    const int*          targets    = (const int*)d_in[3];
    const float*        vectors    = (const float*)d_in[4];
    const int*          timesteps  = (const int*)d_in[5];
    float*              out        = (float*)d_out;

    pst_kernel<<<NENV, NTHR>>>(passengers, accepts, picks, targets, vectors, timesteps, out);
}

// round 16
// speedup vs baseline: 1.1224x; 1.1224x over previous
#include <cuda_runtime.h>
#include <cstdint>

// E=8192 envs, A=128 agents/env, K=512 passengers/env, P=E*K rows x 11 f32 cols.
// Inputs: passengers f32[P,11], accepts/picks bool->32bit [E,A], targets i32[E,A],
//         vectors f32[E,A,4], timesteps i32[E]. Output f32[P,11].
//
// FINAL champion (validated R4 @63.5us, R14 @63.58us; DRAM ~76%, ~6.85 TB/s
// aggregate effective). Fused single kernel, one CTA per env:
//   - 256 threads, 6-deep front-batched float4 stream (per-thread MLP is the
//     binding resource: R5 shallower batch and R15 reg-squeeze both regressed)
//   - flag resolution (count -> dup -> warp-shfl argmin + smem atomicMin)
//     under the bulk-load shadow
//   - bulk store burst after argmin (R9 store-early regressed), default cache
//     policy (R8 .cs evict-first regressed)
//   - agent-driven sparse patches hit lines still L2-resident from the burst
//     (R11/R13 split/CE variants regressed)
// natural regs=40 -> 6 CTAs/SM; do NOT tighten launch bounds (R15: spills).

#define NENV   8192
#define NAG    128
#define NPASS  512
#define NTHR   256
#define ROWF   11
#define VEC4S  ((NPASS * ROWF) / 4)   // 1408 float4 per env chunk (22528 B)
#define TAIL   (VEC4S - 5 * NTHR)     // 128

__global__ __launch_bounds__(NTHR, 6)
void pst_kernel(const float* __restrict__ passengers,
                const unsigned int* __restrict__ accepts,
                const unsigned int* __restrict__ picks,
                const int* __restrict__ targets,
                const float* __restrict__ vectors,
                const int* __restrict__ timesteps,
                float* __restrict__ out)
{
    const int e   = blockIdx.x;
    const int tid = threadIdx.x;

    __shared__ int                cnt[NPASS];      // accept multiplicity per local passenger
    __shared__ unsigned char      picked[NPASS];   // zero-dist pick landed on this row
    __shared__ unsigned long long minkey;          // (dist_bits<<32)|agent argmin
    __shared__ float              ts_s;

    // ---------- phase 0: front-batch the streaming loads (HBM in flight early) ----------
    const float4* __restrict__ src = reinterpret_cast<const float4*>(passengers) + (size_t)e * VEC4S;
    float4*       __restrict__ dst = reinterpret_cast<float4*>(out) + (size_t)e * VEC4S;

    // small per-agent loads first so they're not queued behind 24KB of stream
    const float INF = __int_as_float(0x7f800000);
    float d  = INF;
    int   lt = 0;
    bool  acc = false, pk = false;
    float4 av;
    if (tid < NAG) {
        av  = reinterpret_cast<const float4*>(vectors)[(size_t)e * NAG + tid];
        lt  = __ldg(&targets[e * NAG + tid]) - e * NPASS;       // local idx in [0,512)
        acc = (accepts[e * NAG + tid] != 0u);                   // robust to i32/f32 widening
        pk  = (picks  [e * NAG + tid] != 0u);
    }

    float4 c0 = src[tid];
    float4 c1 = src[tid + 1 * NTHR];
    float4 c2 = src[tid + 2 * NTHR];
    float4 c3 = src[tid + 3 * NTHR];
    float4 c4 = src[tid + 4 * NTHR];
    float4 c5;
    if (tid < TAIL) c5 = src[tid + 5 * NTHR];

    // ---------- phase 1: flag resolution under the load shadow ----------
    for (int i = tid; i < NPASS; i += NTHR) { cnt[i] = 0; picked[i] = 0; }
    if (tid == 0) { ts_s = (float)__ldg(&timesteps[e]); minkey = ~0ull; }

    if (tid < NAG) {
        float dx = av.x - av.z, dy = av.y - av.w;
        d = sqrtf(dx * dx + dy * dy);
        if (av.x == -100.0f && av.y == -100.0f && av.z == -100.0f && av.w == -100.0f) d = INF;
    }
    __syncthreads();                                            // B1: smem init done

    if (acc) atomicAdd(&cnt[lt], 1);
    if (tid < NAG && pk && d < 1e-6f) picked[lt] = 1;
    __syncthreads();                                            // B2: counts + picked visible

    // dup mask + per-env argmin over where(dup, d, inf).
    // JAX argmin: first index achieving min; all-inf -> index 0. Key bits are
    // monotone in the (nonneg) distance; ties resolve to lowest agent index.
    // The reference while-loop converges in exactly one body call: the argmin
    // agent keeps its target, every other duplicate agent is removed.
    bool dup = acc && (cnt[lt] > 1);
    if (tid < NAG) {
        unsigned long long key =
            ((unsigned long long)__float_as_uint(dup ? d : INF) << 32) | (unsigned)tid;
        #pragma unroll
        for (int s = 16; s > 0; s >>= 1) {
            unsigned long long o = __shfl_down_sync(0xffffffffu, key, s);
            if (o < key) key = o;
        }
        if ((tid & 31) == 0) atomicMin(&minkey, key);
    }
    __syncthreads();                                            // B3: argmin resolved
    const int keep = (int)(minkey & 0xffffffffu);

    // ---------- phase 2: bulk store burst ----------
    dst[tid]            = c0;
    dst[tid + 1 * NTHR] = c1;
    dst[tid + 2 * NTHR] = c2;
    dst[tid + 3 * NTHR] = c3;
    dst[tid + 4 * NTHR] = c4;
    if (tid < TAIL) dst[tid + 5 * NTHR] = c5;
    __syncthreads();                                            // B4: bulk before patches

    // ---------- phase 3: agent-driven sparse patches ----------
    // At most one surviving accept agent per row -> unique writer for cols 7/9
    // (and 6 when no pick). Racing pick writers store identical values.
    if (tid < NAG) {
        const float ts = ts_s;
        float* row = reinterpret_cast<float*>(dst) + lt * ROWF;
        bool surviving = acc && !(dup && tid != keep);
        if (surviving) {
            row[7] = (float)tid;
            row[9] = ts;
            if (!picked[lt]) row[6] = 1.0f;
        }
        if (pk && d < 1e-6f) {
            row[6]  = 2.0f;
            row[10] = ts;
        }
    }
}

extern "C" void kernel_launch(void* const* d_in, const int* in_sizes, int n_in,
                              void* d_out, int out_size)
{
    const float*        passengers = (const float*)d_in[0];
    const unsigned int* accepts    = (const unsigned int*)d_in[1];
    const unsigned int* picks      = (const unsigned int*)d_in[2];
    const int*          targets    = (const int*)d_in[3];
    const float*        vectors    = (const float*)d_in[4];
    const int*          timesteps  = (const int*)d_in[5];
    float*              out        = (float*)d_out;

    pst_kernel<<<NENV, NTHR>>>(passengers, accepts, picks, targets, vectors, timesteps, out);
}

// round 17
// speedup vs baseline: 1.1281x; 1.0051x over previous
#include <cuda_runtime.h>
#include <cstdint>

// E=8192 envs, A=128 agents/env, K=512 passengers/env, P=E*K rows x 11 f32 cols.
// Inputs: passengers f32[P,11], accepts/picks bool->32bit [E,A], targets i32[E,A],
//         vectors f32[E,A,4], timesteps i32[E]. Output f32[P,11].
//
// Deep-MLP variant: 128 threads x 11-deep float4 batch (1408 = 128*11 exactly,
// no tail). NTHR == NAG: every thread is an agent -> no tid<NAG divergence.
// __launch_bounds__(128,8) allows up to 64 regs (44 data + flag state) without
// forcing spills. Total in-flight LDG.128/SM: 11264 vs champion's 9216.

#define NENV   8192
#define NAG    128
#define NPASS  512
#define NTHR   128
#define ROWF   11
#define VEC4S  ((NPASS * ROWF) / 4)   // 1408 float4 per env chunk (22528 B)
#define DEPTH  11                      // 1408 / 128

__global__ __launch_bounds__(NTHR, 8)
void pst_kernel(const float* __restrict__ passengers,
                const unsigned int* __restrict__ accepts,
                const unsigned int* __restrict__ picks,
                const int* __restrict__ targets,
                const float* __restrict__ vectors,
                const int* __restrict__ timesteps,
                float* __restrict__ out)
{
    const int e   = blockIdx.x;
    const int tid = threadIdx.x;          // == agent id, 0..127

    __shared__ int                cnt[NPASS];      // accept multiplicity per local passenger
    __shared__ unsigned char      picked[NPASS];   // zero-dist pick landed on this row
    __shared__ unsigned long long minkey;          // (dist_bits<<32)|agent argmin
    __shared__ float              ts_s;

    // ---------- phase 0: per-agent loads, then 11-deep front-batched stream ----------
    const float4* __restrict__ src = reinterpret_cast<const float4*>(passengers) + (size_t)e * VEC4S;
    float4*       __restrict__ dst = reinterpret_cast<float4*>(out) + (size_t)e * VEC4S;

    const float INF = __int_as_float(0x7f800000);
    float4 av = reinterpret_cast<const float4*>(vectors)[(size_t)e * NAG + tid];
    int  lt  = __ldg(&targets[e * NAG + tid]) - e * NPASS;   // local idx in [0,512)
    bool acc = (accepts[e * NAG + tid] != 0u);               // robust to i32/f32 widening
    bool pk  = (picks  [e * NAG + tid] != 0u);

    float4 c[DEPTH];
    #pragma unroll
    for (int k = 0; k < DEPTH; k++) c[k] = src[tid + k * NTHR];

    // ---------- phase 1: flag resolution under the load shadow ----------
    #pragma unroll
    for (int k = 0; k < 4; k++) { cnt[tid * 4 + k] = 0; picked[tid * 4 + k] = 0; }
    if (tid == 0) { ts_s = (float)__ldg(&timesteps[e]); minkey = ~0ull; }

    float dx = av.x - av.z, dy = av.y - av.w;
    float d  = sqrtf(dx * dx + dy * dy);
    if (av.x == -100.0f && av.y == -100.0f && av.z == -100.0f && av.w == -100.0f) d = INF;
    __syncthreads();                                         // B1: smem init done

    if (acc) atomicAdd(&cnt[lt], 1);
    if (pk && d < 1e-6f) picked[lt] = 1;
    __syncthreads();                                         // B2: counts + picked visible

    // dup mask + per-env argmin over where(dup, d, inf).
    // JAX argmin: first index achieving min; all-inf -> index 0. Key bits are
    // monotone in the (nonneg) distance; ties resolve to lowest agent index.
    // The reference while-loop converges in exactly one body call: the argmin
    // agent keeps its target, every other duplicate agent is removed.
    bool dup = acc && (cnt[lt] > 1);
    {
        unsigned long long key =
            ((unsigned long long)__float_as_uint(dup ? d : INF) << 32) | (unsigned)tid;
        #pragma unroll
        for (int s = 16; s > 0; s >>= 1) {
            unsigned long long o = __shfl_down_sync(0xffffffffu, key, s);
            if (o < key) key = o;
        }
        if ((tid & 31) == 0) atomicMin(&minkey, key);
    }
    __syncthreads();                                         // B3: argmin resolved
    const int keep = (int)(minkey & 0xffffffffu);

    // ---------- phase 2: bulk store burst ----------
    #pragma unroll
    for (int k = 0; k < DEPTH; k++) dst[tid + k * NTHR] = c[k];
    __syncthreads();                                         // B4: bulk before patches

    // ---------- phase 3: agent-driven sparse patches ----------
    // At most one surviving accept agent per row -> unique writer for cols 7/9
    // (and 6 when no pick). Racing pick writers store identical values.
    {
        const float ts = ts_s;
        float* row = reinterpret_cast<float*>(dst) + lt * ROWF;
        bool surviving = acc && !(dup && tid != keep);
        if (surviving) {
            row[7] = (float)tid;
            row[9] = ts;
            if (!picked[lt]) row[6] = 1.0f;
        }
        if (pk && d < 1e-6f) {
            row[6]  = 2.0f;
            row[10] = ts;
        }
    }
}

extern "C" void kernel_launch(void* const* d_in, const int* in_sizes, int n_in,
                              void* d_out, int out_size)
{
    const float*        passengers = (const float*)d_in[0];
    const unsigned int* accepts    = (const unsigned int*)d_in[1];
    const unsigned int* picks      = (const unsigned int*)d_in[2];
    const int*          targets    = (const int*)d_in[3];
    const float*        vectors    = (const float*)d_in[4];
    const int*          timesteps  = (const int*)d_in[5];
    float*              out        = (float*)d_out;

    pst_kernel<<<NENV, NTHR>>>(passengers, accepts, picks, targets, vectors, timesteps, out);
}